// round 1
// baseline (speedup 1.0000x reference)
#include <cuda_runtime.h>
#include <math.h>

// ---------------- problem constants ----------------
constexpr int Ls = 2048;     // seq len
constexpr int Bs_ = 8;       // batch
constexpr int Ds = 1024;     // model dim
constexpr int Zs = 128;      // z dim
constexpr int Hs = 2048;     // hidden
constexpr int Ns = 16;       // ema states
constexpr int Es = Zs + Hs + 2 * Ds;  // 4224
constexpr int Rs = Ls * Bs_;          // 16384 rows

// ---------------- device scratch ----------------
__device__ float g_xn[(long)Rs * Ds];
__device__ float g_mx[(long)Rs * Ds];
__device__ float g_v[(long)Rs * Hs];
__device__ float g_base[(long)Rs * Es];
__device__ float g_q[(long)Bs_ * Ls * Zs];
__device__ float g_k[(long)Bs_ * Ls * Zs];
__device__ float g_attn[(long)Bs_ * Ls * Ls];
__device__ float g_hatt[(long)Rs * Hs];
__device__ float g_eq[Ds * Ns];
__device__ float g_ec[Ds * Ns];

__device__ __forceinline__ float sigf(float x) { return 1.f / (1.f + __expf(-x)); }
__device__ __forceinline__ float sigf_acc(float x) { return 1.f / (1.f + expf(-x)); }

// ---------------- layernorm ----------------
__global__ void ln_kernel(const float* __restrict__ x, const float* __restrict__ w,
                          const float* __restrict__ b, float* __restrict__ out) {
    int row = blockIdx.x;
    const float4* xin = (const float4*)(x + (long)row * Ds);
    float4 v = xin[threadIdx.x];
    float s = v.x + v.y + v.z + v.w;
    float ss = v.x * v.x + v.y * v.y + v.z * v.z + v.w * v.w;
#pragma unroll
    for (int o = 16; o; o >>= 1) {
        s += __shfl_xor_sync(0xFFFFFFFFu, s, o);
        ss += __shfl_xor_sync(0xFFFFFFFFu, ss, o);
    }
    __shared__ float sh[16];
    int wid = threadIdx.x >> 5, lid = threadIdx.x & 31;
    if (lid == 0) { sh[wid] = s; sh[8 + wid] = ss; }
    __syncthreads();
    float ts = 0.f, tss = 0.f;
#pragma unroll
    for (int i = 0; i < 8; i++) { ts += sh[i]; tss += sh[8 + i]; }
    float mean = ts * (1.f / Ds);
    float var = tss * (1.f / Ds) - mean * mean;
    float rstd = rsqrtf(var + 1e-5f);
    int c = threadIdx.x * 4;
    float4 o;
    o.x = (v.x - mean) * rstd * w[c + 0] + b[c + 0];
    o.y = (v.y - mean) * rstd * w[c + 1] + b[c + 1];
    o.z = (v.z - mean) * rstd * w[c + 2] + b[c + 2];
    o.w = (v.w - mean) * rstd * w[c + 3] + b[c + 3];
    ((float4*)(out + (long)row * Ds))[threadIdx.x] = o;
}

// ---------------- EMA coefficient prep ----------------
__global__ void ema_prep_k(const float* __restrict__ delta, const float* __restrict__ alpha,
                           const float* __restrict__ beta, const float* __restrict__ gamma,
                           float* __restrict__ eq, float* __restrict__ ec) {
    int i = blockIdx.x * 256 + threadIdx.x;
    if (i >= Ds * Ns) return;
    float p = sigf_acc(delta[i]);
    float qv = 1.f - p * sigf_acc(alpha[i]);
    eq[i] = qv;
    ec[i] = p * beta[i] * gamma[i] * 0.25f;  // 1/sqrt(16)
}

// ---------------- EMA scan + silu(mx) ----------------
// y[t] = sum_n c_n * s_n[t],  s_n[t] = q_n * s_n[t-1] + x[t]
__global__ void ema_scan_k(const float* __restrict__ xn, const float* __restrict__ eq,
                           const float* __restrict__ ec, const float* __restrict__ omega,
                           float* __restrict__ mx) {
    int tid = blockIdx.x * blockDim.x + threadIdx.x;  // 8192 = B*D
    int d = tid & (Ds - 1);
    float q[Ns], c[Ns], s[Ns];
#pragma unroll
    for (int n = 0; n < Ns; n++) { q[n] = eq[d * Ns + n]; c[n] = ec[d * Ns + n]; s[n] = 0.f; }
    float om = omega[d];
    const float* xp = xn + tid;
    float* mp = mx + tid;
    for (int t = 0; t < Ls; t++) {
        float xv = xp[(long)t * (Bs_ * Ds)];
        float y0 = 0.f, y1 = 0.f, y2 = 0.f, y3 = 0.f;
#pragma unroll
        for (int n = 0; n < Ns; n += 4) {
            s[n + 0] = fmaf(q[n + 0], s[n + 0], xv); y0 = fmaf(c[n + 0], s[n + 0], y0);
            s[n + 1] = fmaf(q[n + 1], s[n + 1], xv); y1 = fmaf(c[n + 1], s[n + 1], y1);
            s[n + 2] = fmaf(q[n + 2], s[n + 2], xv); y2 = fmaf(c[n + 2], s[n + 2], y2);
            s[n + 3] = fmaf(q[n + 3], s[n + 3], xv); y3 = fmaf(c[n + 3], s[n + 3], y3);
        }
        float y = (y0 + y1) + (y2 + y3);
        y = fmaf(xv, om, y);
        mp[(long)t * (Bs_ * Ds)] = y * sigf(y);  // silu
    }
}

// ---------------- q/k prep from base's z-slice ----------------
__global__ void qk_prep_k(const float* __restrict__ base, const float* __restrict__ gam,
                          const float* __restrict__ bet, float* __restrict__ q,
                          float* __restrict__ k) {
    int idx = blockIdx.x * 256 + threadIdx.x;  // R*Z
    int row = idx >> 7, zc = idx & 127;
    int l = row >> 3, b = row & 7;
    float z = base[(long)row * Es + Ds + zc];
    long o = ((long)b * Ls + l) * Zs + zc;
    q[o] = fmaf(z, gam[zc], bet[zc]);
    k[o] = fmaf(z, gam[Zs + zc], bet[Zs + zc]);
}

// ---------------- generic tiled SGEMM with fused epilogues ----------------
enum { EP_VSILU = 1, EP_BASE = 2, EP_LAPLACE = 3, EP_MULR = 4, EP_FINAL = 5 };

constexpr int BM = 128, BN = 128, BK = 16;

template <int EP, bool TB>
__global__ __launch_bounds__(256) void gemm_k(
    const float* __restrict__ A, const float* __restrict__ Bm, float* __restrict__ C,
    int K, int lda, int ldb, int ldc,
    long aB, long bB, long cB,
    const float* __restrict__ bias, const float* __restrict__ aux0,
    const float* __restrict__ aux1) {
    __shared__ float As[BK][BM];
    __shared__ float Bsm[BK][BN];
    int bz = blockIdx.z;
    A += bz * aB; Bm += bz * bB; C += bz * cB;
    int row0 = blockIdx.y * BM, col0 = blockIdx.x * BN;
    int tid = threadIdx.x;
    int tx = tid & 15, ty = tid >> 4;
    float acc[8][8];
#pragma unroll
    for (int i = 0; i < 8; i++)
#pragma unroll
        for (int j = 0; j < 8; j++) acc[i][j] = 0.f;

    for (int k0 = 0; k0 < K; k0 += BK) {
#pragma unroll
        for (int u = 0; u < 2; u++) {  // A tile: 512 float4
            int f = tid + u * 256;
            int r = f >> 2, c4 = f & 3;
            float4 t = *(const float4*)(A + (long)(row0 + r) * lda + k0 + c4 * 4);
            As[c4 * 4 + 0][r] = t.x; As[c4 * 4 + 1][r] = t.y;
            As[c4 * 4 + 2][r] = t.z; As[c4 * 4 + 3][r] = t.w;
        }
        if (!TB) {
#pragma unroll
            for (int u = 0; u < 2; u++) {
                int f = tid + u * 256;
                int r = f >> 5, c4 = f & 31;
                float4 t = *(const float4*)(Bm + (long)(k0 + r) * ldb + col0 + c4 * 4);
                *(float4*)&Bsm[r][c4 * 4] = t;
            }
        } else {
#pragma unroll
            for (int u = 0; u < 2; u++) {
                int f = tid + u * 256;
                int n = f >> 2, c4 = f & 3;
                float4 t = *(const float4*)(Bm + (long)(col0 + n) * ldb + k0 + c4 * 4);
                Bsm[c4 * 4 + 0][n] = t.x; Bsm[c4 * 4 + 1][n] = t.y;
                Bsm[c4 * 4 + 2][n] = t.z; Bsm[c4 * 4 + 3][n] = t.w;
            }
        }
        __syncthreads();
#pragma unroll
        for (int kk = 0; kk < BK; kk++) {
            float a[8], bb[8];
            *(float4*)&a[0] = *(const float4*)&As[kk][ty * 8];
            *(float4*)&a[4] = *(const float4*)&As[kk][ty * 8 + 4];
            *(float4*)&bb[0] = *(const float4*)&Bsm[kk][tx * 8];
            *(float4*)&bb[4] = *(const float4*)&Bsm[kk][tx * 8 + 4];
#pragma unroll
            for (int i = 0; i < 8; i++)
#pragma unroll
                for (int j = 0; j < 8; j++) acc[i][j] = fmaf(a[i], bb[j], acc[i][j]);
        }
        __syncthreads();
    }

#pragma unroll
    for (int i = 0; i < 8; i++) {
        int r = row0 + ty * 8 + i;
#pragma unroll
        for (int j = 0; j < 8; j++) {
            int c = col0 + tx * 8 + j;
            float v = acc[i][j];
            if (EP == EP_VSILU) {
                v += bias[c];
                v = v * sigf(v);
            } else if (EP == EP_BASE) {
                v += bias[c];
                if (c < Ds) v = sigf(v);                 // u = sigmoid
                else if (c < Ds + Zs + Hs) v = v * sigf(v);  // z,r = silu
                // else hx passthrough
            } else if (EP == EP_LAPLACE) {
                v = v * (1.f / (float)Ls) + aux0[c - r];  // aux0 = rel_pos + 2047
                v = 0.5f * (1.f + erff((v - 0.707107f) * 2.5066287f));
            } else if (EP == EP_MULR) {
                // r-gate: silu'd base col 1152+c, row = l*B + bz
                v *= aux0[((long)r * Bs_ + bz) * Es + (Ds + Zs) + c];
            } else if (EP == EP_FINAL) {
                float hx = aux0[(long)r * Es + (Ds + Zs + Hs) + c];
                float u = aux0[(long)r * Es + c];
                float xv = aux1[(long)r * Ds + c];
                float h = hx + v + bias[c];
                h = h * sigf(h);
                v = xv + u * (h - xv);
            }
            C[(long)r * ldc + c] = v;
        }
    }
}

// ---------------- launch ----------------
extern "C" void kernel_launch(void* const* d_in, const int* in_sizes, int n_in,
                              void* d_out, int out_size) {
    const float* x        = (const float*)d_in[0];
    const float* delta    = (const float*)d_in[1];
    const float* alpha    = (const float*)d_in[2];
    const float* beta_ema = (const float*)d_in[3];
    const float* gamma_e  = (const float*)d_in[4];
    const float* omega    = (const float*)d_in[5];
    const float* v_w      = (const float*)d_in[6];
    const float* v_b      = (const float*)d_in[7];
    const float* mx_w     = (const float*)d_in[8];
    const float* mx_b     = (const float*)d_in[9];
    const float* h_w      = (const float*)d_in[10];
    const float* h_b      = (const float*)d_in[11];
    const float* qk_gamma = (const float*)d_in[12];
    const float* qk_beta  = (const float*)d_in[13];
    const float* rel_pos  = (const float*)d_in[14];
    const float* ln_w     = (const float*)d_in[15];
    const float* ln_b     = (const float*)d_in[16];
    float* out = (float*)d_out;

    float *xn, *mx, *v, *base, *q, *k, *attn, *hatt, *eq, *ec;
    cudaGetSymbolAddress((void**)&xn, g_xn);
    cudaGetSymbolAddress((void**)&mx, g_mx);
    cudaGetSymbolAddress((void**)&v, g_v);
    cudaGetSymbolAddress((void**)&base, g_base);
    cudaGetSymbolAddress((void**)&q, g_q);
    cudaGetSymbolAddress((void**)&k, g_k);
    cudaGetSymbolAddress((void**)&attn, g_attn);
    cudaGetSymbolAddress((void**)&hatt, g_hatt);
    cudaGetSymbolAddress((void**)&eq, g_eq);
    cudaGetSymbolAddress((void**)&ec, g_ec);

    // 1) layernorm
    ln_kernel<<<Rs, 256>>>(x, ln_w, ln_b, xn);
    // 2) EMA coefficients
    ema_prep_k<<<(Ds * Ns + 255) / 256, 256>>>(delta, alpha, beta_ema, gamma_e, eq, ec);
    // 3) EMA scan -> mx (silu fused)
    ema_scan_k<<<(Bs_ * Ds) / 256, 256>>>(xn, eq, ec, omega, mx);
    // 4) v = silu(xn @ v_w + v_b)
    {
        dim3 g(Hs / BN, Rs / BM, 1);
        gemm_k<EP_VSILU, false><<<g, 256>>>(xn, v_w, v, Ds, Ds, Hs, Hs, 0, 0, 0,
                                            v_b, nullptr, nullptr);
    }
    // 5) base = act(mx @ mx_w + mx_b)  (sigmoid / silu / identity by column)
    {
        dim3 g(Es / BN, Rs / BM, 1);
        gemm_k<EP_BASE, false><<<g, 256>>>(mx, mx_w, base, Ds, Ds, Es, Es, 0, 0, 0,
                                           mx_b, nullptr, nullptr);
    }
    // 6) q,k from z-slice
    qk_prep_k<<<(Rs * Zs) / 256, 256>>>(base, qk_gamma, qk_beta, q, k);
    // 7) attn = laplace(q @ k^T / L + bias)   (batched NT)
    {
        dim3 g(Ls / BN, Ls / BM, Bs_);
        gemm_k<EP_LAPLACE, true><<<g, 256>>>(q, k, attn, Zs, Zs, Zs, Ls,
                                             (long)Ls * Zs, (long)Ls * Zs, (long)Ls * Ls,
                                             nullptr, rel_pos + 2047, nullptr);
    }
    // 8) hatt = (attn @ vb) * r   (batched NN, strided B = v as (L,B,H))
    {
        dim3 g(Hs / BN, Ls / BM, Bs_);
        gemm_k<EP_MULR, false><<<g, 256>>>(attn, v, hatt, Ls, Ls, Bs_ * Hs, Bs_ * Hs,
                                           (long)Ls * Ls, (long)Hs, (long)Hs,
                                           nullptr, base, nullptr);
    }
    // 9) out = x + u * (silu(hx + hatt @ h_w + h_b) - x)
    {
        dim3 g(Ds / BN, Rs / BM, 1);
        gemm_k<EP_FINAL, false><<<g, 256>>>(hatt, h_w, out, Hs, Hs, Ds, Ds, 0, 0, 0,
                                            h_b, base, x);
    }
}

// round 2
// speedup vs baseline: 3.5780x; 3.5780x over previous
#include <cuda_runtime.h>
#include <math.h>
#include <stdint.h>

// ---------------- problem constants ----------------
constexpr int Ls = 2048;     // seq len
constexpr int Bs_ = 8;       // batch
constexpr int Ds = 1024;     // model dim
constexpr int Zs = 128;      // z dim
constexpr int Hs = 2048;     // hidden
constexpr int Ns = 16;       // ema states
constexpr int Es = Zs + Hs + 2 * Ds;  // 4224
constexpr int Rs = Ls * Bs_;          // 16384 rows
constexpr int NC = 16;                // ema chunks
constexpr int CL = Ls / NC;           // 128 steps per chunk

// ---------------- device scratch ----------------
__device__ float g_xn[(long)Rs * Ds];
__device__ float g_mx[(long)Rs * Ds];
__device__ float g_v[(long)Rs * Hs];
__device__ float g_base[(long)Rs * Es];
__device__ float g_q[(long)Bs_ * Ls * Zs];
__device__ float g_k[(long)Bs_ * Ls * Zs];
__device__ float g_attn[(long)Bs_ * Ls * Ls];
__device__ float g_hatt[(long)Rs * Hs];
__device__ float g_eq[Ds * Ns];
__device__ float g_ec[Ds * Ns];
__device__ float g_carry[(long)NC * Bs_ * Ds * Ns];

__device__ __forceinline__ float sigf(float x) { return 1.f / (1.f + __expf(-x)); }
__device__ __forceinline__ float sigf_acc(float x) { return 1.f / (1.f + expf(-x)); }

// ---------------- layernorm ----------------
__global__ void ln_kernel(const float* __restrict__ x, const float* __restrict__ w,
                          const float* __restrict__ b, float* __restrict__ out) {
    int row = blockIdx.x;
    const float4* xin = (const float4*)(x + (long)row * Ds);
    float4 v = xin[threadIdx.x];
    float s = v.x + v.y + v.z + v.w;
    float ss = v.x * v.x + v.y * v.y + v.z * v.z + v.w * v.w;
#pragma unroll
    for (int o = 16; o; o >>= 1) {
        s += __shfl_xor_sync(0xFFFFFFFFu, s, o);
        ss += __shfl_xor_sync(0xFFFFFFFFu, ss, o);
    }
    __shared__ float sh[16];
    int wid = threadIdx.x >> 5, lid = threadIdx.x & 31;
    if (lid == 0) { sh[wid] = s; sh[8 + wid] = ss; }
    __syncthreads();
    float ts = 0.f, tss = 0.f;
#pragma unroll
    for (int i = 0; i < 8; i++) { ts += sh[i]; tss += sh[8 + i]; }
    float mean = ts * (1.f / Ds);
    float var = tss * (1.f / Ds) - mean * mean;
    float rstd = rsqrtf(var + 1e-5f);
    int c = threadIdx.x * 4;
    float4 o;
    o.x = (v.x - mean) * rstd * w[c + 0] + b[c + 0];
    o.y = (v.y - mean) * rstd * w[c + 1] + b[c + 1];
    o.z = (v.z - mean) * rstd * w[c + 2] + b[c + 2];
    o.w = (v.w - mean) * rstd * w[c + 3] + b[c + 3];
    ((float4*)(out + (long)row * Ds))[threadIdx.x] = o;
}

// ---------------- EMA coefficient prep ----------------
__global__ void ema_prep_k(const float* __restrict__ delta, const float* __restrict__ alpha,
                           const float* __restrict__ beta, const float* __restrict__ gamma,
                           float* __restrict__ eq, float* __restrict__ ec) {
    int i = blockIdx.x * 256 + threadIdx.x;
    if (i >= Ds * Ns) return;
    float p = sigf_acc(delta[i]);
    float qv = 1.f - p * sigf_acc(alpha[i]);
    eq[i] = qv;
    ec[i] = p * beta[i] * gamma[i] * 0.25f;  // 1/sqrt(16)
}

// ---------------- chunk-parallel EMA scan ----------------
// Recurrence: s_n[t] = q_n s_n[t-1] + x[t];  y[t] = sum_n c_n s_n[t] + omega*x[t]
// Phase A: per-chunk local scan from s=0, record chunk-final states.
__global__ void ema_scanA(const float* __restrict__ xn, const float* __restrict__ eq,
                          float* __restrict__ carry) {
    int tid = blockIdx.x * blockDim.x + threadIdx.x;  // B*D*NC
    int bd = tid & (Bs_ * Ds - 1);
    int ch = tid >> 13;
    int d = bd & (Ds - 1);
    float q[Ns], s[Ns];
#pragma unroll
    for (int n = 0; n < Ns; n++) { q[n] = eq[d * Ns + n]; s[n] = 0.f; }
    const float* xp = xn + bd + (long)ch * CL * (Bs_ * Ds);
    for (int t = 0; t < CL; t++) {
        float xv = xp[(long)t * (Bs_ * Ds)];
#pragma unroll
        for (int n = 0; n < Ns; n++) s[n] = fmaf(q[n], s[n], xv);
    }
    float* cp = carry + ((long)ch * (Bs_ * Ds) + bd) * Ns;
#pragma unroll
    for (int n = 0; n < Ns; n++) cp[n] = s[n];
}

// Phase B: serial carry across NC chunks; rewrite carry[] to hold INCOMING state per chunk.
__global__ void ema_carry_k(const float* __restrict__ eq, float* __restrict__ carry) {
    int i = blockIdx.x * 256 + threadIdx.x;  // B*D*Ns
    int bd = i >> 4, n = i & 15;
    int d = bd & (Ds - 1);
    float q = eq[d * Ns + n];
    float qc = q;
#pragma unroll
    for (int j = 0; j < 7; j++) qc *= qc;  // q^128
    float sg = 0.f;
    for (int ch = 0; ch < NC; ch++) {
        long idx = ((long)ch * (Bs_ * Ds) + bd) * Ns + n;
        float loc = carry[idx];
        carry[idx] = sg;               // incoming global state for chunk ch
        sg = fmaf(qc, sg, loc);        // global state at end of chunk ch
    }
}

// Phase C: re-scan each chunk starting from incoming state, emit silu(y).
__global__ void ema_scanC(const float* __restrict__ xn, const float* __restrict__ eq,
                          const float* __restrict__ ec, const float* __restrict__ omega,
                          const float* __restrict__ carry, float* __restrict__ mx) {
    int tid = blockIdx.x * blockDim.x + threadIdx.x;
    int bd = tid & (Bs_ * Ds - 1);
    int ch = tid >> 13;
    int d = bd & (Ds - 1);
    float q[Ns], c[Ns], s[Ns];
    const float* cp = carry + ((long)ch * (Bs_ * Ds) + bd) * Ns;
#pragma unroll
    for (int n = 0; n < Ns; n++) {
        q[n] = eq[d * Ns + n];
        c[n] = ec[d * Ns + n];
        s[n] = cp[n];
    }
    float om = omega[d];
    const float* xp = xn + bd + (long)ch * CL * (Bs_ * Ds);
    float* mp = mx + bd + (long)ch * CL * (Bs_ * Ds);
    for (int t = 0; t < CL; t++) {
        float xv = xp[(long)t * (Bs_ * Ds)];
        float y0 = 0.f, y1 = 0.f, y2 = 0.f, y3 = 0.f;
#pragma unroll
        for (int n = 0; n < Ns; n += 4) {
            s[n + 0] = fmaf(q[n + 0], s[n + 0], xv); y0 = fmaf(c[n + 0], s[n + 0], y0);
            s[n + 1] = fmaf(q[n + 1], s[n + 1], xv); y1 = fmaf(c[n + 1], s[n + 1], y1);
            s[n + 2] = fmaf(q[n + 2], s[n + 2], xv); y2 = fmaf(c[n + 2], s[n + 2], y2);
            s[n + 3] = fmaf(q[n + 3], s[n + 3], xv); y3 = fmaf(c[n + 3], s[n + 3], y3);
        }
        float y = (y0 + y1) + (y2 + y3);
        y = fmaf(xv, om, y);
        mp[(long)t * (Bs_ * Ds)] = y * sigf(y);
    }
}

// ---------------- q/k prep from base's z-slice ----------------
__global__ void qk_prep_k(const float* __restrict__ base, const float* __restrict__ gam,
                          const float* __restrict__ bet, float* __restrict__ q,
                          float* __restrict__ k) {
    int idx = blockIdx.x * 256 + threadIdx.x;  // R*Z
    int row = idx >> 7, zc = idx & 127;
    int l = row >> 3, b = row & 7;
    float z = base[(long)row * Es + Ds + zc];
    long o = ((long)b * Ls + l) * Zs + zc;
    q[o] = fmaf(z, gam[zc], bet[zc]);
    k[o] = fmaf(z, gam[Zs + zc], bet[Zs + zc]);
}

// ---------------- tf32 tensor-core GEMM with fused epilogues ----------------
enum { EP_VSILU = 1, EP_BASE = 2, EP_LAPLACE = 3, EP_MULR = 4, EP_FINAL = 5 };

constexpr int BM = 128, BN = 128, BK = 16;

__device__ __forceinline__ uint32_t f2tf(float x) {
    uint32_t u;
    asm("cvt.rna.tf32.f32 %0, %1;" : "=r"(u) : "f"(x));
    return u;
}
__device__ __forceinline__ void mma_tf32(float* d, const uint32_t* a, const uint32_t* b) {
    asm volatile(
        "mma.sync.aligned.m16n8k8.row.col.f32.tf32.tf32.f32 "
        "{%0,%1,%2,%3}, {%4,%5,%6,%7}, {%8,%9}, {%0,%1,%2,%3};"
        : "+f"(d[0]), "+f"(d[1]), "+f"(d[2]), "+f"(d[3])
        : "r"(a[0]), "r"(a[1]), "r"(a[2]), "r"(a[3]), "r"(b[0]), "r"(b[1]));
}
__device__ __forceinline__ void cp16(void* smem, const void* g) {
    uint32_t s = (uint32_t)__cvta_generic_to_shared(smem);
    asm volatile("cp.async.cg.shared.global [%0], [%1], 16;" :: "r"(s), "l"(g));
}
__device__ __forceinline__ void cp_commit() { asm volatile("cp.async.commit_group;"); }
template <int N>
__device__ __forceinline__ void cp_wait() { asm volatile("cp.async.wait_group %0;" :: "n"(N)); }

template <int EP>
__device__ __forceinline__ float epilog(float v, int r, int c, int bz,
                                        const float* __restrict__ bias,
                                        const float* __restrict__ aux0,
                                        const float* __restrict__ aux1) {
    if (EP == EP_VSILU) {
        v += bias[c];
        v = v * sigf(v);
    } else if (EP == EP_BASE) {
        v += bias[c];
        if (c < Ds) v = sigf(v);                     // u = sigmoid
        else if (c < Ds + Zs + Hs) v = v * sigf(v);  // z,r = silu
        // else hx passthrough
    } else if (EP == EP_LAPLACE) {
        v = v * (1.f / (float)Ls) + aux0[c - r];     // aux0 = rel_pos + 2047
        v = 0.5f * (1.f + erff((v - 0.707107f) * 2.5066287f));
    } else if (EP == EP_MULR) {
        v *= aux0[((long)r * Bs_ + bz) * Es + (Ds + Zs) + c];
    } else if (EP == EP_FINAL) {
        float hx = aux0[(long)r * Es + (Ds + Zs + Hs) + c];
        float u = aux0[(long)r * Es + c];
        float xv = aux1[(long)r * Ds + c];
        float h = hx + v + bias[c];
        h = h * sigf(h);
        v = xv + u * (h - xv);
    }
    return v;
}

template <int EP, bool TB>
__global__ void __launch_bounds__(256) gemm_tc(
    const float* __restrict__ A, const float* __restrict__ Bm, float* __restrict__ C,
    int K, int lda, int ldb, int ldc, long aB, long bB, long cB,
    const float* __restrict__ bias, const float* __restrict__ aux0,
    const float* __restrict__ aux1) {
    constexpr int LDAS = BK + 4;                       // 20
    constexpr int BSZ = TB ? BN * (BK + 4) : BK * (BN + 8);
    __shared__ float As[2][BM * LDAS];
    __shared__ float Bs[2][BSZ];
    int bz = blockIdx.z;
    A += bz * aB; Bm += bz * bB; C += bz * cB;
    int row0 = blockIdx.y * BM, col0 = blockIdx.x * BN;
    int tid = threadIdx.x;
    int lane = tid & 31, wid = tid >> 5;
    int wm = wid >> 2, wn = wid & 3;   // 2 x 4 warp grid
    int g = lane >> 2, t = lane & 3;

    float acc[4][4][4];
#pragma unroll
    for (int i = 0; i < 4; i++)
#pragma unroll
        for (int j = 0; j < 4; j++)
#pragma unroll
            for (int h = 0; h < 4; h++) acc[i][j][h] = 0.f;

    auto load_stage = [&](int s, int k0) {
#pragma unroll
        for (int u = 0; u < 2; u++) {
            int f = tid + u * 256;
            int m = f >> 2, c4 = f & 3;
            cp16(&As[s][m * LDAS + c4 * 4], A + (long)(row0 + m) * lda + k0 + c4 * 4);
        }
        if (TB) {
#pragma unroll
            for (int u = 0; u < 2; u++) {
                int f = tid + u * 256;
                int n = f >> 2, c4 = f & 3;
                cp16(&Bs[s][n * LDAS + c4 * 4], Bm + (long)(col0 + n) * ldb + k0 + c4 * 4);
            }
        } else {
#pragma unroll
            for (int u = 0; u < 2; u++) {
                int f = tid + u * 256;
                int kr = f >> 5, c4 = f & 31;
                cp16(&Bs[s][kr * (BN + 8) + c4 * 4], Bm + (long)(k0 + kr) * ldb + col0 + c4 * 4);
            }
        }
        cp_commit();
    };

    int niter = K / BK;
    load_stage(0, 0);
    for (int it = 0; it < niter; it++) {
        int s = it & 1;
        if (it + 1 < niter) {
            load_stage(s ^ 1, (it + 1) * BK);
            cp_wait<1>();
        } else {
            cp_wait<0>();
        }
        __syncthreads();
#pragma unroll
        for (int kh = 0; kh < 2; kh++) {
            int kk = kh * 8;
            uint32_t af[4][4], bf[4][2];
#pragma unroll
            for (int mi = 0; mi < 4; mi++) {
                int m = wm * 64 + mi * 16;
                const float* ap = &As[s][0];
                af[mi][0] = f2tf(ap[(m + g) * LDAS + kk + t]);
                af[mi][1] = f2tf(ap[(m + g + 8) * LDAS + kk + t]);
                af[mi][2] = f2tf(ap[(m + g) * LDAS + kk + t + 4]);
                af[mi][3] = f2tf(ap[(m + g + 8) * LDAS + kk + t + 4]);
            }
#pragma unroll
            for (int ni = 0; ni < 4; ni++) {
                int n = wn * 32 + ni * 8;
                if (TB) {
                    bf[ni][0] = f2tf(Bs[s][(n + g) * LDAS + kk + t]);
                    bf[ni][1] = f2tf(Bs[s][(n + g) * LDAS + kk + t + 4]);
                } else {
                    bf[ni][0] = f2tf(Bs[s][(kk + t) * (BN + 8) + n + g]);
                    bf[ni][1] = f2tf(Bs[s][(kk + t + 4) * (BN + 8) + n + g]);
                }
            }
#pragma unroll
            for (int mi = 0; mi < 4; mi++)
#pragma unroll
                for (int ni = 0; ni < 4; ni++)
                    mma_tf32(acc[mi][ni], af[mi], bf[ni]);
        }
        __syncthreads();
    }

#pragma unroll
    for (int mi = 0; mi < 4; mi++) {
#pragma unroll
        for (int ni = 0; ni < 4; ni++) {
            int rb = row0 + wm * 64 + mi * 16 + g;
            int cb = col0 + wn * 32 + ni * 8 + t * 2;
#pragma unroll
            for (int h = 0; h < 2; h++) {
                int r = rb + h * 8;
                float2 o;
                o.x = epilog<EP>(acc[mi][ni][h * 2 + 0], r, cb, bz, bias, aux0, aux1);
                o.y = epilog<EP>(acc[mi][ni][h * 2 + 1], r, cb + 1, bz, bias, aux0, aux1);
                *(float2*)&C[(long)r * ldc + cb] = o;
            }
        }
    }
}

// ---------------- launch ----------------
extern "C" void kernel_launch(void* const* d_in, const int* in_sizes, int n_in,
                              void* d_out, int out_size) {
    const float* x        = (const float*)d_in[0];
    const float* delta    = (const float*)d_in[1];
    const float* alpha    = (const float*)d_in[2];
    const float* beta_ema = (const float*)d_in[3];
    const float* gamma_e  = (const float*)d_in[4];
    const float* omega    = (const float*)d_in[5];
    const float* v_w      = (const float*)d_in[6];
    const float* v_b      = (const float*)d_in[7];
    const float* mx_w     = (const float*)d_in[8];
    const float* mx_b     = (const float*)d_in[9];
    const float* h_w      = (const float*)d_in[10];
    const float* h_b      = (const float*)d_in[11];
    const float* qk_gamma = (const float*)d_in[12];
    const float* qk_beta  = (const float*)d_in[13];
    const float* rel_pos  = (const float*)d_in[14];
    const float* ln_w     = (const float*)d_in[15];
    const float* ln_b     = (const float*)d_in[16];
    float* out = (float*)d_out;

    float *xn, *mx, *v, *base, *q, *k, *attn, *hatt, *eq, *ec, *carry;
    cudaGetSymbolAddress((void**)&xn, g_xn);
    cudaGetSymbolAddress((void**)&mx, g_mx);
    cudaGetSymbolAddress((void**)&v, g_v);
    cudaGetSymbolAddress((void**)&base, g_base);
    cudaGetSymbolAddress((void**)&q, g_q);
    cudaGetSymbolAddress((void**)&k, g_k);
    cudaGetSymbolAddress((void**)&attn, g_attn);
    cudaGetSymbolAddress((void**)&hatt, g_hatt);
    cudaGetSymbolAddress((void**)&eq, g_eq);
    cudaGetSymbolAddress((void**)&ec, g_ec);
    cudaGetSymbolAddress((void**)&carry, g_carry);

    // 1) layernorm
    ln_kernel<<<Rs, 256>>>(x, ln_w, ln_b, xn);
    // 2) EMA coefficients
    ema_prep_k<<<(Ds * Ns + 255) / 256, 256>>>(delta, alpha, beta_ema, gamma_e, eq, ec);
    // 3) chunk-parallel EMA scan -> mx (silu fused)
    ema_scanA<<<(Bs_ * Ds * NC) / 256, 256>>>(xn, eq, carry);
    ema_carry_k<<<(Bs_ * Ds * Ns) / 256, 256>>>(eq, carry);
    ema_scanC<<<(Bs_ * Ds * NC) / 256, 256>>>(xn, eq, ec, omega, carry, mx);
    // 4) v = silu(xn @ v_w + v_b)
    {
        dim3 gr(Hs / BN, Rs / BM, 1);
        gemm_tc<EP_VSILU, false><<<gr, 256>>>(xn, v_w, v, Ds, Ds, Hs, Hs, 0, 0, 0,
                                              v_b, nullptr, nullptr);
    }
    // 5) base = act(mx @ mx_w + mx_b)
    {
        dim3 gr(Es / BN, Rs / BM, 1);
        gemm_tc<EP_BASE, false><<<gr, 256>>>(mx, mx_w, base, Ds, Ds, Es, Es, 0, 0, 0,
                                             mx_b, nullptr, nullptr);
    }
    // 6) q,k from z-slice
    qk_prep_k<<<(Rs * Zs) / 256, 256>>>(base, qk_gamma, qk_beta, q, k);
    // 7) attn = laplace(q @ k^T / L + bias)
    {
        dim3 gr(Ls / BN, Ls / BM, Bs_);
        gemm_tc<EP_LAPLACE, true><<<gr, 256>>>(q, k, attn, Zs, Zs, Zs, Ls,
                                               (long)Ls * Zs, (long)Ls * Zs, (long)Ls * Ls,
                                               nullptr, rel_pos + 2047, nullptr);
    }
    // 8) hatt = (attn @ vb) * r
    {
        dim3 gr(Hs / BN, Ls / BM, Bs_);
        gemm_tc<EP_MULR, false><<<gr, 256>>>(attn, v, hatt, Ls, Ls, Bs_ * Hs, Bs_ * Hs,
                                             (long)Ls * Ls, (long)Hs, (long)Hs,
                                             nullptr, base, nullptr);
    }
    // 9) out = x + u * (silu(hx + hatt @ h_w + h_b) - x)
    {
        dim3 gr(Ds / BN, Rs / BM, 1);
        gemm_tc<EP_FINAL, false><<<gr, 256>>>(hatt, h_w, out, Hs, Hs, Ds, Ds, 0, 0, 0,
                                              h_b, base, x);
    }
}